// round 1
// baseline (speedup 1.0000x reference)
#include <cuda_runtime.h>
#include <math.h>

#define B      32
#define NITEMS 16384
#define D      128
#define IDIM   64

// ---------------- device scratch (no allocation allowed) ----------------
__device__ float g_scores[B * NITEMS];   // 2 MB, fits L2
__device__ float g_u[B * D];             // per-batch score vector (scale folded in)
__device__ float g_const[B];             // per-batch score constant (scale folded in)
__device__ float g_tau[B];
__device__ float g_asum[B];              // sum of relu(z - tau)
__device__ float g_sacc[B * D];          // sum_n relu(score-tau) * g[b,n]

__device__ __forceinline__ float gelu_f(float x) {
    // exact (erf) gelu, matching torch nn.GELU default / jax approximate=False
    return 0.5f * x * (1.0f + erff(x * 0.7071067811865476f));
}

// ---------------- init: zero the sparse accumulator ----------------
__global__ void init_kernel() {
    int i = blockIdx.x * blockDim.x + threadIdx.x;
    if (i < B * D) g_sacc[i] = 0.0f;
}

// ---------------- prep: per-batch query path + folded vectors ----------------
// u[b]  = scale * wx2 @ (wkp @ q[b])
// c[b]  = scale * (bx2 . (wkp @ q[b]) + q[b] . bkp)
__global__ void prep_kernel(const float* __restrict__ x_query,
                            const float* __restrict__ wq1, const float* __restrict__ bq1,
                            const float* __restrict__ wq2, const float* __restrict__ bq2,
                            const float* __restrict__ wqp, const float* __restrict__ bqp,
                            const float* __restrict__ wkp, const float* __restrict__ bkp,
                            const float* __restrict__ wx2, const float* __restrict__ bx2) {
    int b = blockIdx.x;
    int j = threadIdx.x;
    __shared__ float h1[D], hq[D], qv[D], av[D], red[D];

    float xq = x_query[b];
    h1[j] = gelu_f(fmaf(xq, wq1[j], bq1[j]));
    __syncthreads();

    float acc = bq2[j];
    #pragma unroll 8
    for (int i = 0; i < D; i++) acc = fmaf(h1[i], wq2[i * D + j], acc);
    hq[j] = acc;
    __syncthreads();

    acc = bqp[j];
    #pragma unroll 8
    for (int i = 0; i < D; i++) acc = fmaf(hq[i], wqp[i * D + j], acc);
    qv[j] = acc;                       // q[b][j]
    __syncthreads();

    acc = 0.0f;                        // a = wkp @ q : a_j = sum_i wkp[j,i] q[i]
    #pragma unroll 8
    for (int i = 0; i < D; i++) acc = fmaf(wkp[j * D + i], qv[i], acc);
    av[j] = acc;
    __syncthreads();

    float u = 0.0f;                    // u_j = sum_i wx2[j,i] a[i]
    #pragma unroll 8
    for (int i = 0; i < D; i++) u = fmaf(wx2[j * D + i], av[i], u);

    const float scale = 0.08838834764831845f;   // 128^-0.5
    g_u[b * D + j] = u * scale;

    red[j] = bx2[j] * av[j] + qv[j] * bkp[j];
    __syncthreads();
    for (int s = 64; s > 0; s >>= 1) {
        if (j < s) red[j] += red[j + s];
        __syncthreads();
    }
    if (j == 0) g_const[b] = red[0] * scale;
}

// ---------------- pass 1: scores[b,n] = g . u[b] + c[b] ----------------
__global__ void __launch_bounds__(256) pass1_kernel(const float* __restrict__ x_items,
                                                    const float* __restrict__ wx1,
                                                    const float* __restrict__ bx1) {
    __shared__ float ws[IDIM * D];   // 32 KB weight tile
    __shared__ float bs[D];
    __shared__ float us[D];

    int b = blockIdx.y;
    int t = threadIdx.x;
    int n = blockIdx.x * 256 + t;

    for (int k = t; k < IDIM * D; k += 256) ws[k] = wx1[k];
    if (t < D) { bs[t] = bx1[t]; us[t] = g_u[b * D + t]; }
    __syncthreads();

    const float4* xp = (const float4*)(x_items + ((size_t)b * NITEMS + (size_t)n) * IDIM);
    float xr[IDIM];
    #pragma unroll
    for (int k = 0; k < 16; k++) {
        float4 v = xp[k];
        xr[4 * k + 0] = v.x; xr[4 * k + 1] = v.y;
        xr[4 * k + 2] = v.z; xr[4 * k + 3] = v.w;
    }

    float score = g_const[b];
    #pragma unroll 1
    for (int j = 0; j < D; j += 4) {
        float a0 = bs[j], a1 = bs[j + 1], a2 = bs[j + 2], a3 = bs[j + 3];
        #pragma unroll
        for (int i = 0; i < IDIM; i++) {
            float4 w = *(const float4*)&ws[i * D + j];   // broadcast LDS.128
            float x = xr[i];
            a0 = fmaf(x, w.x, a0);
            a1 = fmaf(x, w.y, a1);
            a2 = fmaf(x, w.z, a2);
            a3 = fmaf(x, w.w, a3);
        }
        score = fmaf(gelu_f(a0), us[j],     score);
        score = fmaf(gelu_f(a1), us[j + 1], score);
        score = fmaf(gelu_f(a2), us[j + 2], score);
        score = fmaf(gelu_f(a3), us[j + 3], score);
    }
    g_scores[b * NITEMS + n] = score;
}

// ---------------- bisection for sparsemax tau (register-resident) ----------------
__global__ void __launch_bounds__(512) bisect_kernel() {
    int b = blockIdx.x;
    int t = threadIdx.x;
    int w = t >> 5, l = t & 31;

    const float* sc = g_scores + b * NITEMS;
    float z[32];
    #pragma unroll
    for (int k = 0; k < 32; k++) z[k] = sc[t + k * 512];

    // block max
    float m = z[0];
    #pragma unroll
    for (int k = 1; k < 32; k++) m = fmaxf(m, z[k]);
    __shared__ float red[16];
    __shared__ float sh_flag;
    #pragma unroll
    for (int o = 16; o > 0; o >>= 1) m = fmaxf(m, __shfl_xor_sync(0xffffffffu, m, o));
    if (l == 0) red[w] = m;
    __syncthreads();
    if (t == 0) {
        float v = red[0];
        for (int i = 1; i < 16; i++) v = fmaxf(v, red[i]);
        red[0] = v;
    }
    __syncthreads();
    float zmax = red[0];
    __syncthreads();

    float lo = zmax - 1.0f, hi = zmax;
    for (int it = 0; it < 40; it++) {
        float mid = 0.5f * (lo + hi);
        float s = 0.0f;
        #pragma unroll
        for (int k = 0; k < 32; k++) s += fmaxf(z[k] - mid, 0.0f);
        #pragma unroll
        for (int o = 16; o > 0; o >>= 1) s += __shfl_xor_sync(0xffffffffu, s, o);
        __syncthreads();
        if (l == 0) red[w] = s;
        __syncthreads();
        if (t == 0) {
            float v = 0.0f;
            for (int i = 0; i < 16; i++) v += red[i];
            sh_flag = (v >= 1.0f) ? 1.0f : 0.0f;
        }
        __syncthreads();
        if (sh_flag > 0.5f) lo = mid; else hi = mid;
    }

    float tau = 0.5f * (lo + hi);
    float s = 0.0f;
    #pragma unroll
    for (int k = 0; k < 32; k++) s += fmaxf(z[k] - tau, 0.0f);
    #pragma unroll
    for (int o = 16; o > 0; o >>= 1) s += __shfl_xor_sync(0xffffffffu, s, o);
    __syncthreads();
    if (l == 0) red[w] = s;
    __syncthreads();
    if (t == 0) {
        float v = 0.0f;
        for (int i = 0; i < 16; i++) v += red[i];
        g_tau[b] = tau;
        g_asum[b] = v;
    }
}

// ---------------- pass 2: s[b] = sum over support of (score - tau) * g[b,n] ----------------
__global__ void __launch_bounds__(256) pass2_kernel(const float* __restrict__ x_items,
                                                    const float* __restrict__ wx1,
                                                    const float* __restrict__ bx1) {
    int b = blockIdx.y;
    int t = threadIdx.x;
    int n = blockIdx.x * 256 + t;

    float tau = g_tau[b];
    float wgt = g_scores[b * NITEMS + n] - tau;
    int any = __syncthreads_or(wgt > 0.0f);
    if (!any) return;   // vast majority of blocks: sparsemax support is tiny

    __shared__ float ws[IDIM * D];
    __shared__ float bs[D];
    for (int k = t; k < IDIM * D; k += 256) ws[k] = wx1[k];
    if (t < D) bs[t] = bx1[t];
    __syncthreads();

    if (wgt > 0.0f) {
        const float4* xp = (const float4*)(x_items + ((size_t)b * NITEMS + (size_t)n) * IDIM);
        float xr[IDIM];
        #pragma unroll
        for (int k = 0; k < 16; k++) {
            float4 v = xp[k];
            xr[4 * k + 0] = v.x; xr[4 * k + 1] = v.y;
            xr[4 * k + 2] = v.z; xr[4 * k + 3] = v.w;
        }
        #pragma unroll 1
        for (int j = 0; j < D; j++) {
            float a = bs[j];
            #pragma unroll
            for (int i = 0; i < IDIM; i++) a = fmaf(xr[i], ws[i * D + j], a);
            atomicAdd(&g_sacc[b * D + j], wgt * gelu_f(a));
        }
    }
}

// ---------------- finalize: z -> output MLP ----------------
__global__ void finalize_kernel(float* __restrict__ out,
                                const float* __restrict__ wx2, const float* __restrict__ bx2,
                                const float* __restrict__ wvp, const float* __restrict__ bvp,
                                const float* __restrict__ wp1, const float* __restrict__ bp1,
                                const float* __restrict__ wp2, const float* __restrict__ bp2) {
    int b = blockIdx.x;
    int j = threadIdx.x;
    __shared__ float sn[D], hb[D], zz[D], pp[D];

    sn[j] = g_sacc[b * D + j] / g_asum[b];     // normalized attn-weighted g sum
    __syncthreads();

    float acc = bx2[j];
    #pragma unroll 8
    for (int i = 0; i < D; i++) acc = fmaf(sn[i], wx2[i * D + j], acc);
    hb[j] = acc;
    __syncthreads();

    acc = bvp[j];
    #pragma unroll 8
    for (int i = 0; i < D; i++) acc = fmaf(hb[i], wvp[i * D + j], acc);
    zz[j] = acc;
    __syncthreads();

    acc = bp1[j];
    #pragma unroll 8
    for (int i = 0; i < D; i++) acc = fmaf(zz[i], wp1[i * D + j], acc);
    pp[j] = gelu_f(acc);
    __syncthreads();

    if (j < 10) {
        acc = bp2[j];
        #pragma unroll 8
        for (int i = 0; i < D; i++) acc = fmaf(pp[i], wp2[i * 10 + j], acc);
        out[b * 10 + j] = acc;
    }
}

// ---------------- launch ----------------
extern "C" void kernel_launch(void* const* d_in, const int* in_sizes, int n_in,
                              void* d_out, int out_size) {
    const float* x_items = (const float*)d_in[0];
    const float* x_query = (const float*)d_in[1];
    const float* wx1 = (const float*)d_in[2];  const float* bx1 = (const float*)d_in[3];
    const float* wx2 = (const float*)d_in[4];  const float* bx2 = (const float*)d_in[5];
    const float* wq1 = (const float*)d_in[6];  const float* bq1 = (const float*)d_in[7];
    const float* wq2 = (const float*)d_in[8];  const float* bq2 = (const float*)d_in[9];
    const float* wqp = (const float*)d_in[10]; const float* bqp = (const float*)d_in[11];
    const float* wkp = (const float*)d_in[12]; const float* bkp = (const float*)d_in[13];
    const float* wvp = (const float*)d_in[14]; const float* bvp = (const float*)d_in[15];
    const float* wp1 = (const float*)d_in[16]; const float* bp1 = (const float*)d_in[17];
    const float* wp2 = (const float*)d_in[18]; const float* bp2 = (const float*)d_in[19];
    float* out = (float*)d_out;

    init_kernel<<<16, 256>>>();
    prep_kernel<<<B, D>>>(x_query, wq1, bq1, wq2, bq2, wqp, bqp, wkp, bkp, wx2, bx2);
    dim3 grid(NITEMS / 256, B);
    pass1_kernel<<<grid, 256>>>(x_items, wx1, bx1);
    bisect_kernel<<<B, 512>>>();
    pass2_kernel<<<grid, 256>>>(x_items, wx1, bx1);
    finalize_kernel<<<B, D>>>(out, wx2, bx2, wvp, bvp, wp1, bp1, wp2, bp2);
}